// round 2
// baseline (speedup 1.0000x reference)
#include <cuda_runtime.h>

#define N_NODES 100000
#define MAX_E   1600000
#define D       128
#define SCAN_BLOCKS ((N_NODES + 255) / 256)   // 391

// ---------------- device scratch (static allocation, per the rules) ----------
__device__ int   g_is64;
__device__ int   g_src[MAX_E];
__device__ int   g_dst[MAX_E];
__device__ int   g_cnt[N_NODES];
__device__ int   g_scan[SCAN_BLOCKS * 256];
__device__ int   g_bsum[512];
__device__ int   g_rowptr[N_NODES + 1];
__device__ int   g_cursor[N_NODES];
__device__ int   g_colidx[MAX_E];
__device__ float g_agg[(size_t)N_NODES * D];   // aggregation output (reused)
__device__ float g_h1 [(size_t)N_NODES * D];   // relu(agg @ W1 + b1)

// ---------------- dtype detection + normalization ----------------------------
// If the buffer holds int64 values < 2^31, every odd 32-bit word of the first
// 512 words is zero. If int32 (random 0..99999), essentially all are nonzero.
__global__ void detect_kernel(const int* __restrict__ p) {
    __shared__ int any;
    if (threadIdx.x == 0) any = 0;
    __syncthreads();
    int v = p[threadIdx.x * 2 + 1];   // odd words among first 512 int32s
    if (v != 0) atomicOr(&any, 1);
    __syncthreads();
    if (threadIdx.x == 0) g_is64 = (any == 0);
}

__global__ void convert_kernel(const void* __restrict__ src,
                               const void* __restrict__ dst, int E) {
    int i = blockIdx.x * blockDim.x + threadIdx.x;
    if (i >= E) return;
    if (g_is64) {
        g_src[i] = (int)((const long long*)src)[i];
        g_dst[i] = (int)((const long long*)dst)[i];
    } else {
        g_src[i] = ((const int*)src)[i];
        g_dst[i] = ((const int*)dst)[i];
    }
}

// ---------------- CSR build ---------------------------------------------------
__global__ void zero_cnt_kernel() {
    int i = blockIdx.x * blockDim.x + threadIdx.x;
    if (i < N_NODES) g_cnt[i] = 0;
}

__global__ void count_kernel(int E) {
    int i = blockIdx.x * blockDim.x + threadIdx.x;
    if (i < E) {
        unsigned d = (unsigned)g_dst[i];
        if (d < N_NODES) atomicAdd(&g_cnt[d], 1);
    }
}

// inclusive scan of 256-element chunks (Hillis–Steele in smem)
__global__ void scan_pass1() {
    __shared__ int s[256];
    int t = threadIdx.x;
    int i = blockIdx.x * 256 + t;
    int v = (i < N_NODES) ? g_cnt[i] : 0;
    s[t] = v;
    __syncthreads();
#pragma unroll
    for (int off = 1; off < 256; off <<= 1) {
        int x = (t >= off) ? s[t - off] : 0;
        __syncthreads();
        s[t] += x;
        __syncthreads();
    }
    g_scan[i] = s[t];
    if (t == 255) g_bsum[blockIdx.x] = s[255];
}

// exclusive scan of block sums (serial in smem; SCAN_BLOCKS=391 is tiny)
__global__ void scan_pass2(int nblk) {
    __shared__ int s[512];
    int t = threadIdx.x;
    if (t < nblk) s[t] = g_bsum[t];
    __syncthreads();
    if (t == 0) {
        int off = 0;
        for (int b = 0; b < nblk; b++) { int x = s[b]; s[b] = off; off += x; }
    }
    __syncthreads();
    if (t < nblk) g_bsum[t] = s[t];
}

__global__ void scan_pass3() {
    int i = blockIdx.x * blockDim.x + threadIdx.x;
    if (i >= N_NODES) return;
    int incl = g_scan[i] + g_bsum[i >> 8];
    g_rowptr[i + 1] = incl;
    g_cursor[i] = incl - g_cnt[i];      // exclusive start
    if (i == 0) g_rowptr[0] = 0;
}

__global__ void fill_kernel(int E) {
    int i = blockIdx.x * blockDim.x + threadIdx.x;
    if (i >= E) return;
    unsigned d = (unsigned)g_dst[i];
    unsigned s = (unsigned)g_src[i];
    if (d >= N_NODES || s >= N_NODES) return;
    int pos = atomicAdd(&g_cursor[d], 1);
    g_colidx[pos] = (int)s;
}

// ---------------- gather-side mean aggregation: one warp per node ------------
__global__ void agg_kernel(const float* __restrict__ in, float* __restrict__ out) {
    int warp = (blockIdx.x * blockDim.x + threadIdx.x) >> 5;
    int lane = threadIdx.x & 31;
    if (warp >= N_NODES) return;
    int s = g_rowptr[warp];
    int e = g_rowptr[warp + 1];

    float4 acc = make_float4(0.f, 0.f, 0.f, 0.f);
    int i = s;
    for (; i + 4 <= e; i += 4) {
        int c0 = g_colidx[i + 0];
        int c1 = g_colidx[i + 1];
        int c2 = g_colidx[i + 2];
        int c3 = g_colidx[i + 3];
        float4 v0 = __ldg((const float4*)(in + (size_t)c0 * D) + lane);
        float4 v1 = __ldg((const float4*)(in + (size_t)c1 * D) + lane);
        float4 v2 = __ldg((const float4*)(in + (size_t)c2 * D) + lane);
        float4 v3 = __ldg((const float4*)(in + (size_t)c3 * D) + lane);
        acc.x += (v0.x + v1.x) + (v2.x + v3.x);
        acc.y += (v0.y + v1.y) + (v2.y + v3.y);
        acc.z += (v0.z + v1.z) + (v2.z + v3.z);
        acc.w += (v0.w + v1.w) + (v2.w + v3.w);
    }
    for (; i < e; i++) {
        int c = g_colidx[i];
        float4 v = __ldg((const float4*)(in + (size_t)c * D) + lane);
        acc.x += v.x; acc.y += v.y; acc.z += v.z; acc.w += v.w;
    }
    int cnt = e - s;
    float inv = 1.f / (float)(cnt > 1 ? cnt : 1);
    acc.x *= inv; acc.y *= inv; acc.z *= inv; acc.w *= inv;
    ((float4*)(out + (size_t)warp * D))[lane] = acc;
}

// ---------------- fp32 tiled GEMM: C[M,BN] = act(A[M,128] @ W[128,BN] + b) ----
// BM=64 rows per block, full K=128, 256 threads (16x16), TM=4, TN=BN/16.
// A tile stored transposed in smem [K=128][68] for conflict-free float4 reads.
template <int BN, bool RELU>
__global__ void gemm_kernel(const float* __restrict__ A, const float* __restrict__ W,
                            const float* __restrict__ bias, float* __restrict__ C) {
    extern __shared__ float sm[];
    float* As = sm;              // [128][68]
    float* Ws = sm + 128 * 68;   // [128][BN]
    const int tid = threadIdx.x;
    const int m0 = blockIdx.x * 64;

    // load full W (128 x BN) via float4
    for (int i = tid * 4; i < 128 * BN; i += 256 * 4)
        *(float4*)&Ws[i] = *(const float4*)&W[i];

    // load A tile (64 x 128) transposed into As[k][m]
    for (int i = tid; i < 2048; i += 256) {        // 2048 float4s
        int r = i >> 5;            // row within tile (0..63)
        int c = (i & 31) << 2;     // k start (0..124)
        float4 v = make_float4(0.f, 0.f, 0.f, 0.f);
        if (m0 + r < N_NODES)
            v = *(const float4*)&A[(size_t)(m0 + r) * 128 + c];
        As[(c + 0) * 68 + r] = v.x;
        As[(c + 1) * 68 + r] = v.y;
        As[(c + 2) * 68 + r] = v.z;
        As[(c + 3) * 68 + r] = v.w;
    }
    __syncthreads();

    const int tx = tid & 15, ty = tid >> 4;
    constexpr int TN = BN / 16;
    float acc[4][TN];
#pragma unroll
    for (int i = 0; i < 4; i++)
#pragma unroll
        for (int j = 0; j < TN; j++) acc[i][j] = 0.f;

#pragma unroll 4
    for (int k = 0; k < 128; k++) {
        float4 a = *(const float4*)&As[k * 68 + ty * 4];
        float w[TN];
#pragma unroll
        for (int j = 0; j < TN; j += 4)
            *(float4*)&w[j] = *(const float4*)&Ws[k * BN + tx * TN + j];
#pragma unroll
        for (int j = 0; j < TN; j++) {
            acc[0][j] += a.x * w[j];
            acc[1][j] += a.y * w[j];
            acc[2][j] += a.z * w[j];
            acc[3][j] += a.w * w[j];
        }
    }

#pragma unroll
    for (int i = 0; i < 4; i++) {
        int m = m0 + ty * 4 + i;
        if (m < N_NODES) {
#pragma unroll
            for (int j = 0; j < TN; j++) {
                float v = acc[i][j] + bias[tx * TN + j];
                if (RELU) v = fmaxf(v, 0.f);
                C[(size_t)m * BN + tx * TN + j] = v;
            }
        }
    }
}

// ---------------- launch ------------------------------------------------------
extern "C" void kernel_launch(void* const* d_in, const int* in_sizes, int n_in,
                              void* d_out, int out_size) {
    const float* features = (const float*)d_in[0];
    const float* W1       = (const float*)d_in[1];
    const float* b1       = (const float*)d_in[2];
    const float* W2       = (const float*)d_in[3];
    const float* b2       = (const float*)d_in[4];
    const void*  src      = d_in[5];
    const void*  dst      = d_in[6];
    float*       out      = (float*)d_out;
    int E = in_sizes[5];
    if (E > MAX_E) E = MAX_E;

    float *agg_p, *h1_p;
    cudaGetSymbolAddress((void**)&agg_p, g_agg);
    cudaGetSymbolAddress((void**)&h1_p,  g_h1);

    const int SMEM1 = (128 * 68 + 128 * 128) * 4;  // 100352 B
    const int SMEM2 = (128 * 68 + 128 * 64) * 4;   //  67584 B
    cudaFuncSetAttribute(gemm_kernel<128, true>,
                         cudaFuncAttributeMaxDynamicSharedMemorySize, SMEM1);
    cudaFuncSetAttribute(gemm_kernel<64, false>,
                         cudaFuncAttributeMaxDynamicSharedMemorySize, SMEM2);

    const int TB = 256;
    // normalize edge indices (handles int32 or int64 input)
    detect_kernel<<<1, 256>>>((const int*)dst);
    convert_kernel<<<(E + TB - 1) / TB, TB>>>(src, dst, E);

    // CSR build (per-launch, deterministic work)
    zero_cnt_kernel<<<(N_NODES + TB - 1) / TB, TB>>>();
    count_kernel<<<(E + TB - 1) / TB, TB>>>(E);
    scan_pass1<<<SCAN_BLOCKS, 256>>>();
    scan_pass2<<<1, 512>>>(SCAN_BLOCKS);
    scan_pass3<<<SCAN_BLOCKS, 256>>>();
    fill_kernel<<<(E + TB - 1) / TB, TB>>>(E);

    // layer 0: mean agg -> relu(x @ W1 + b1)
    int agg_blocks = (N_NODES * 32 + TB - 1) / TB;
    agg_kernel<<<agg_blocks, TB>>>(features, agg_p);
    gemm_kernel<128, true><<<(N_NODES + 63) / 64, 256, SMEM1>>>(agg_p, W1, b1, h1_p);

    // layer 1: mean agg -> x @ W2 + b2
    agg_kernel<<<agg_blocks, TB>>>(h1_p, agg_p);
    gemm_kernel<64, false><<<(N_NODES + 63) / 64, 256, SMEM2>>>(agg_p, W2, b2, out);
}

// round 3
// speedup vs baseline: 1.0690x; 1.0690x over previous
#include <cuda_runtime.h>

#define N_NODES 100000
#define MAX_E   1600000
#define D       128
#define SCAN_BLOCKS ((N_NODES + 255) / 256)   // 391

// ---------------- device scratch ----------------------------------------------
__device__ int   g_is64;
__device__ int   g_src[MAX_E];
__device__ int   g_dst[MAX_E];
__device__ int   g_cnt[N_NODES];
__device__ int   g_scan[SCAN_BLOCKS * 256];
__device__ int   g_bsum[512];
__device__ int   g_rowptr[N_NODES + 1];
__device__ int   g_cursor[N_NODES];
__device__ int   g_colidx[MAX_E];
__device__ float g_agg[(size_t)N_NODES * D];   // scratch A (agg out / t2)
__device__ float g_h1 [(size_t)N_NODES * D];   // scratch B (h1)

// ---------------- f32x2 helpers -------------------------------------------------
__device__ __forceinline__ unsigned long long pack2(float x) {
    unsigned long long r;
    asm("mov.b64 %0, {%1, %1};" : "=l"(r) : "r"(__float_as_uint(x)));
    return r;
}
__device__ __forceinline__ unsigned long long fma2(unsigned long long a,
                                                   unsigned long long b,
                                                   unsigned long long c) {
    unsigned long long d;
    asm("fma.rn.f32x2 %0, %1, %2, %3;" : "=l"(d) : "l"(a), "l"(b), "l"(c));
    return d;
}
__device__ __forceinline__ void unpack2(unsigned long long v, float& lo, float& hi) {
    unsigned int a, b;
    asm("mov.b64 {%0, %1}, %2;" : "=r"(a), "=r"(b) : "l"(v));
    lo = __uint_as_float(a); hi = __uint_as_float(b);
}

// ---------------- dtype detect + fused convert/count ---------------------------
__global__ void detect_kernel(const int* __restrict__ p) {
    __shared__ int any;
    if (threadIdx.x == 0) any = 0;
    __syncthreads();
    if (p[threadIdx.x * 2 + 1] != 0) atomicOr(&any, 1);
    __syncthreads();
    if (threadIdx.x == 0) g_is64 = (any == 0);
}

__global__ void convcount_kernel(const void* __restrict__ src,
                                 const void* __restrict__ dst, int E) {
    int i = blockIdx.x * blockDim.x + threadIdx.x;
    if (i >= E) return;
    int s, d;
    if (g_is64) {
        s = (int)((const long long*)src)[i];
        d = (int)((const long long*)dst)[i];
    } else {
        s = ((const int*)src)[i];
        d = ((const int*)dst)[i];
    }
    g_src[i] = s;
    g_dst[i] = d;
    if ((unsigned)d < N_NODES) atomicAdd(&g_cnt[d], 1);
}

__global__ void zero_cnt_kernel() {
    int i = blockIdx.x * blockDim.x + threadIdx.x;
    if (i < N_NODES) g_cnt[i] = 0;
}

// ---------------- scan ----------------------------------------------------------
__global__ void scan_pass1() {
    __shared__ int s[256];
    int t = threadIdx.x;
    int i = blockIdx.x * 256 + t;
    int v = (i < N_NODES) ? g_cnt[i] : 0;
    s[t] = v;
    __syncthreads();
#pragma unroll
    for (int off = 1; off < 256; off <<= 1) {
        int x = (t >= off) ? s[t - off] : 0;
        __syncthreads();
        s[t] += x;
        __syncthreads();
    }
    g_scan[i] = s[t];
    if (t == 255) g_bsum[blockIdx.x] = s[255];
}

__global__ void scan_pass2(int nblk) {
    __shared__ int s[512];
    int t = threadIdx.x;
    if (t < nblk) s[t] = g_bsum[t];
    __syncthreads();
    if (t == 0) {
        int off = 0;
        for (int b = 0; b < nblk; b++) { int x = s[b]; s[b] = off; off += x; }
    }
    __syncthreads();
    if (t < nblk) g_bsum[t] = s[t];
}

__global__ void scan_pass3() {
    int i = blockIdx.x * blockDim.x + threadIdx.x;
    if (i >= N_NODES) return;
    int incl = g_scan[i] + g_bsum[i >> 8];
    g_rowptr[i + 1] = incl;
    g_cursor[i] = incl - g_cnt[i];
    if (i == 0) g_rowptr[0] = 0;
}

__global__ void fill_kernel(int E) {
    int i = blockIdx.x * blockDim.x + threadIdx.x;
    if (i >= E) return;
    unsigned d = (unsigned)g_dst[i];
    unsigned s = (unsigned)g_src[i];
    if (d >= N_NODES || s >= N_NODES) return;
    int pos = atomicAdd(&g_cursor[d], 1);
    g_colidx[pos] = (int)s;
}

// ---------------- mean aggregation, 128-wide (warp/node, float4/lane) ----------
__global__ void agg_kernel(const float* __restrict__ in, float* __restrict__ out) {
    int warp = (blockIdx.x * blockDim.x + threadIdx.x) >> 5;
    int lane = threadIdx.x & 31;
    if (warp >= N_NODES) return;
    int s = g_rowptr[warp];
    int e = g_rowptr[warp + 1];

    float4 acc = make_float4(0.f, 0.f, 0.f, 0.f);
    int i = s;
    for (; i + 4 <= e; i += 4) {
        int c0 = g_colidx[i + 0];
        int c1 = g_colidx[i + 1];
        int c2 = g_colidx[i + 2];
        int c3 = g_colidx[i + 3];
        float4 v0 = __ldg((const float4*)(in + (size_t)c0 * D) + lane);
        float4 v1 = __ldg((const float4*)(in + (size_t)c1 * D) + lane);
        float4 v2 = __ldg((const float4*)(in + (size_t)c2 * D) + lane);
        float4 v3 = __ldg((const float4*)(in + (size_t)c3 * D) + lane);
        acc.x += (v0.x + v1.x) + (v2.x + v3.x);
        acc.y += (v0.y + v1.y) + (v2.y + v3.y);
        acc.z += (v0.z + v1.z) + (v2.z + v3.z);
        acc.w += (v0.w + v1.w) + (v2.w + v3.w);
    }
    for (; i < e; i++) {
        int c = g_colidx[i];
        float4 v = __ldg((const float4*)(in + (size_t)c * D) + lane);
        acc.x += v.x; acc.y += v.y; acc.z += v.z; acc.w += v.w;
    }
    int cnt = e - s;
    float inv = 1.f / (float)(cnt > 1 ? cnt : 1);
    acc.x *= inv; acc.y *= inv; acc.z *= inv; acc.w *= inv;
    ((float4*)(out + (size_t)warp * D))[lane] = acc;
}

// ---------------- mean aggregation, 64-wide + bias epilogue (warp/node) --------
__global__ void agg64_kernel(const float* __restrict__ in,
                             const float* __restrict__ bias,
                             float* __restrict__ out) {
    int warp = (blockIdx.x * blockDim.x + threadIdx.x) >> 5;
    int lane = threadIdx.x & 31;
    if (warp >= N_NODES) return;
    int s = g_rowptr[warp];
    int e = g_rowptr[warp + 1];

    float2 acc = make_float2(0.f, 0.f);
    int i = s;
    for (; i + 4 <= e; i += 4) {
        int c0 = g_colidx[i + 0];
        int c1 = g_colidx[i + 1];
        int c2 = g_colidx[i + 2];
        int c3 = g_colidx[i + 3];
        float2 v0 = __ldg((const float2*)(in + (size_t)c0 * 64) + lane);
        float2 v1 = __ldg((const float2*)(in + (size_t)c1 * 64) + lane);
        float2 v2 = __ldg((const float2*)(in + (size_t)c2 * 64) + lane);
        float2 v3 = __ldg((const float2*)(in + (size_t)c3 * 64) + lane);
        acc.x += (v0.x + v1.x) + (v2.x + v3.x);
        acc.y += (v0.y + v1.y) + (v2.y + v3.y);
    }
    for (; i < e; i++) {
        int c = g_colidx[i];
        float2 v = __ldg((const float2*)(in + (size_t)c * 64) + lane);
        acc.x += v.x; acc.y += v.y;
    }
    int cnt = e - s;
    float inv = 1.f / (float)(cnt > 1 ? cnt : 1);
    float2 b = __ldg((const float2*)bias + lane);
    float2 o;
    o.x = acc.x * inv + b.x;
    o.y = acc.y * inv + b.y;
    ((float2*)(out + (size_t)warp * 64))[lane] = o;
}

// ---------------- fp32 GEMM with packed f32x2 FMA -------------------------------
// C[M,BN] = act(A[M,128] @ W[128,BN] + b). BM=64, 256 threads (16x16),
// TM=4 rows, TN=BN/16 cols, accumulators packed in f32x2 along N.
template <int BN, bool RELU, bool HAS_BIAS>
__global__ void gemm_kernel(const float* __restrict__ A, const float* __restrict__ W,
                            const float* __restrict__ bias, float* __restrict__ C) {
    extern __shared__ float sm[];
    float* As = sm;              // [128][68] transposed
    float* Ws = sm + 128 * 68;   // [128][BN]
    const int tid = threadIdx.x;
    const int m0 = blockIdx.x * 64;

    for (int i = tid * 4; i < 128 * BN; i += 256 * 4)
        *(float4*)&Ws[i] = *(const float4*)&W[i];

    for (int i = tid; i < 2048; i += 256) {
        int r = i >> 5;
        int c = (i & 31) << 2;
        float4 v = make_float4(0.f, 0.f, 0.f, 0.f);
        if (m0 + r < N_NODES)
            v = *(const float4*)&A[(size_t)(m0 + r) * 128 + c];
        As[(c + 0) * 68 + r] = v.x;
        As[(c + 1) * 68 + r] = v.y;
        As[(c + 2) * 68 + r] = v.z;
        As[(c + 3) * 68 + r] = v.w;
    }
    __syncthreads();

    const int tx = tid & 15, ty = tid >> 4;
    constexpr int TN = BN / 16;     // 8 or 4
    constexpr int TP = TN / 2;      // f32x2 pairs: 4 or 2
    unsigned long long acc[4][TP];
#pragma unroll
    for (int i = 0; i < 4; i++)
#pragma unroll
        for (int j = 0; j < TP; j++) acc[i][j] = 0ULL;

#pragma unroll 4
    for (int k = 0; k < 128; k++) {
        float4 a = *(const float4*)&As[k * 68 + ty * 4];
        unsigned long long a2[4];
        a2[0] = pack2(a.x); a2[1] = pack2(a.y);
        a2[2] = pack2(a.z); a2[3] = pack2(a.w);
        unsigned long long w2[TP];
#pragma unroll
        for (int j = 0; j < TP; j += 2) {
            float4 wv = *(const float4*)&Ws[k * BN + tx * TN + j * 2];
            w2[j + 0] = __double_as_longlong(*(double*)&wv.x);
            w2[j + 1] = __double_as_longlong(*(double*)&wv.z);
        }
#pragma unroll
        for (int i = 0; i < 4; i++)
#pragma unroll
            for (int j = 0; j < TP; j++)
                acc[i][j] = fma2(a2[i], w2[j], acc[i][j]);
    }

#pragma unroll
    for (int i = 0; i < 4; i++) {
        int m = m0 + ty * 4 + i;
        if (m < N_NODES) {
#pragma unroll
            for (int j = 0; j < TP; j++) {
                float lo, hi;
                unpack2(acc[i][j], lo, hi);
                int n = tx * TN + j * 2;
                if (HAS_BIAS) { lo += bias[n]; hi += bias[n + 1]; }
                if (RELU) { lo = fmaxf(lo, 0.f); hi = fmaxf(hi, 0.f); }
                C[(size_t)m * BN + n]     = lo;
                C[(size_t)m * BN + n + 1] = hi;
            }
        }
    }
}

// ---------------- launch ---------------------------------------------------------
extern "C" void kernel_launch(void* const* d_in, const int* in_sizes, int n_in,
                              void* d_out, int out_size) {
    const float* features = (const float*)d_in[0];
    const float* W1       = (const float*)d_in[1];
    const float* b1       = (const float*)d_in[2];
    const float* W2       = (const float*)d_in[3];
    const float* b2       = (const float*)d_in[4];
    const void*  src      = d_in[5];
    const void*  dst      = d_in[6];
    float*       out      = (float*)d_out;
    int E = in_sizes[5];
    if (E > MAX_E) E = MAX_E;

    float *agg_p, *h1_p;
    cudaGetSymbolAddress((void**)&agg_p, g_agg);
    cudaGetSymbolAddress((void**)&h1_p,  g_h1);

    const int SMEM1 = (128 * 68 + 128 * 128) * 4;  // 100352 B
    const int SMEM2 = (128 * 68 + 128 * 64) * 4;   //  67584 B
    cudaFuncSetAttribute(gemm_kernel<128, true, true>,
                         cudaFuncAttributeMaxDynamicSharedMemorySize, SMEM1);
    cudaFuncSetAttribute(gemm_kernel<64, false, false>,
                         cudaFuncAttributeMaxDynamicSharedMemorySize, SMEM2);

    const int TB = 256;
    // CSR build
    zero_cnt_kernel<<<(N_NODES + TB - 1) / TB, TB>>>();
    detect_kernel<<<1, 256>>>((const int*)dst);
    convcount_kernel<<<(E + TB - 1) / TB, TB>>>(src, dst, E);
    scan_pass1<<<SCAN_BLOCKS, 256>>>();
    scan_pass2<<<1, 512>>>(SCAN_BLOCKS);
    scan_pass3<<<SCAN_BLOCKS, 256>>>();
    fill_kernel<<<(E + TB - 1) / TB, TB>>>(E);

    int agg_blocks = (N_NODES * 32 + TB - 1) / TB;

    // layer 0: h1 = relu(S(X) @ W1 + b1)
    agg_kernel<<<agg_blocks, TB>>>(features, agg_p);
    gemm_kernel<128, true, true><<<(N_NODES + 63) / 64, 256, SMEM1>>>(agg_p, W1, b1, h1_p);

    // layer 1 (reordered): out = S(h1 @ W2) + b2   [S commutes with linear map]
    gemm_kernel<64, false, false><<<(N_NODES + 63) / 64, 256, SMEM2>>>(h1_p, W2, nullptr, agg_p);
    agg64_kernel<<<agg_blocks, TB>>>(agg_p, b2, out);
}

// round 4
// speedup vs baseline: 1.3213x; 1.2360x over previous
#include <cuda_runtime.h>

#define N_NODES 100000
#define MAX_E   1600000
#define D       128
#define SCAN_BLOCKS ((N_NODES + 255) / 256)   // 391

// ---------------- device scratch ----------------------------------------------
__device__ int   g_is64;
__device__ int   g_src[MAX_E];
__device__ int   g_dst[MAX_E];
__device__ int   g_cnt[N_NODES];
__device__ int   g_scan[SCAN_BLOCKS * 256];
__device__ int   g_bsum[512];
__device__ int   g_rowptr[N_NODES + 1];
__device__ int   g_cursor[N_NODES];
__device__ int   g_colidx[MAX_E];
__device__ float g_agg[(size_t)N_NODES * D];   // agg1 out / t2 (64-wide) reuse
__device__ float g_t2 [(size_t)N_NODES * 64];  // t2 = h1 @ W2

// ---------------- f32x2 helpers -------------------------------------------------
typedef unsigned long long ull;
__device__ __forceinline__ ull pack2(float x) {
    ull r;
    asm("mov.b64 %0, {%1, %1};" : "=l"(r) : "r"(__float_as_uint(x)));
    return r;
}
__device__ __forceinline__ ull fma2(ull a, ull b, ull c) {
    ull d;
    asm("fma.rn.f32x2 %0, %1, %2, %3;" : "=l"(d) : "l"(a), "l"(b), "l"(c));
    return d;
}
__device__ __forceinline__ void unpack2(ull v, float& lo, float& hi) {
    unsigned int a, b;
    asm("mov.b64 {%0, %1}, %2;" : "=r"(a), "=r"(b) : "l"(v));
    lo = __uint_as_float(a); hi = __uint_as_float(b);
}

// ---------------- dtype detect + fused convert/count ---------------------------
__global__ void detect_kernel(const int* __restrict__ p) {
    __shared__ int any;
    if (threadIdx.x == 0) any = 0;
    __syncthreads();
    if (p[threadIdx.x * 2 + 1] != 0) atomicOr(&any, 1);
    __syncthreads();
    if (threadIdx.x == 0) g_is64 = (any == 0);
}

__global__ void convcount_kernel(const void* __restrict__ src,
                                 const void* __restrict__ dst, int E) {
    int i = blockIdx.x * blockDim.x + threadIdx.x;
    if (i >= E) return;
    int s, d;
    if (g_is64) {
        s = (int)((const long long*)src)[i];
        d = (int)((const long long*)dst)[i];
    } else {
        s = ((const int*)src)[i];
        d = ((const int*)dst)[i];
    }
    g_src[i] = s;
    g_dst[i] = d;
    if ((unsigned)d < N_NODES) atomicAdd(&g_cnt[d], 1);
}

// ---------------- scan ----------------------------------------------------------
__global__ void scan_pass1() {
    __shared__ int s[256];
    int t = threadIdx.x;
    int i = blockIdx.x * 256 + t;
    int v = (i < N_NODES) ? g_cnt[i] : 0;
    s[t] = v;
    __syncthreads();
#pragma unroll
    for (int off = 1; off < 256; off <<= 1) {
        int x = (t >= off) ? s[t - off] : 0;
        __syncthreads();
        s[t] += x;
        __syncthreads();
    }
    g_scan[i] = s[t];
    if (t == 255) g_bsum[blockIdx.x] = s[255];
}

__global__ void scan_pass2(int nblk) {
    __shared__ int s[512];
    int t = threadIdx.x;
    if (t < nblk) s[t] = g_bsum[t];
    __syncthreads();
    if (t == 0) {
        int off = 0;
        for (int b = 0; b < nblk; b++) { int x = s[b]; s[b] = off; off += x; }
    }
    __syncthreads();
    if (t < nblk) g_bsum[t] = s[t];
}

__global__ void scan_pass3() {
    int i = blockIdx.x * blockDim.x + threadIdx.x;
    if (i >= N_NODES) return;
    int incl = g_scan[i] + g_bsum[i >> 8];
    g_rowptr[i + 1] = incl;
    g_cursor[i] = incl - g_cnt[i];
    if (i == 0) g_rowptr[0] = 0;
}

__global__ void fill_kernel(int E) {
    int i = blockIdx.x * blockDim.x + threadIdx.x;
    if (i >= E) return;
    unsigned d = (unsigned)g_dst[i];
    unsigned s = (unsigned)g_src[i];
    if (d >= N_NODES || s >= N_NODES) return;
    int pos = atomicAdd(&g_cursor[d], 1);
    g_colidx[pos] = (int)s;
}

// ---------------- mean aggregation, 128-wide (warp/node) ------------------------
__global__ void agg_kernel(const float* __restrict__ in, float* __restrict__ out) {
    int warp = (blockIdx.x * blockDim.x + threadIdx.x) >> 5;
    int lane = threadIdx.x & 31;
    if (warp >= N_NODES) return;
    int s = __ldg(&g_rowptr[warp]);
    int e = __ldg(&g_rowptr[warp + 1]);

    float4 acc = make_float4(0.f, 0.f, 0.f, 0.f);
    int i = s;
    for (; i + 4 <= e; i += 4) {
        int c0 = __ldg(&g_colidx[i + 0]);
        int c1 = __ldg(&g_colidx[i + 1]);
        int c2 = __ldg(&g_colidx[i + 2]);
        int c3 = __ldg(&g_colidx[i + 3]);
        float4 v0 = __ldg((const float4*)(in + (size_t)c0 * D) + lane);
        float4 v1 = __ldg((const float4*)(in + (size_t)c1 * D) + lane);
        float4 v2 = __ldg((const float4*)(in + (size_t)c2 * D) + lane);
        float4 v3 = __ldg((const float4*)(in + (size_t)c3 * D) + lane);
        acc.x += (v0.x + v1.x) + (v2.x + v3.x);
        acc.y += (v0.y + v1.y) + (v2.y + v3.y);
        acc.z += (v0.z + v1.z) + (v2.z + v3.z);
        acc.w += (v0.w + v1.w) + (v2.w + v3.w);
    }
    for (; i < e; i++) {
        int c = __ldg(&g_colidx[i]);
        float4 v = __ldg((const float4*)(in + (size_t)c * D) + lane);
        acc.x += v.x; acc.y += v.y; acc.z += v.z; acc.w += v.w;
    }
    int cnt = e - s;
    float inv = 1.f / (float)(cnt > 1 ? cnt : 1);
    acc.x *= inv; acc.y *= inv; acc.z *= inv; acc.w *= inv;
    ((float4*)(out + (size_t)warp * D))[lane] = acc;
}

// ---------------- mean aggregation, 64-wide + bias epilogue ---------------------
__global__ void agg64_kernel(const float* __restrict__ in,
                             const float* __restrict__ bias,
                             float* __restrict__ out) {
    int warp = (blockIdx.x * blockDim.x + threadIdx.x) >> 5;
    int lane = threadIdx.x & 31;
    if (warp >= N_NODES) return;
    int s = __ldg(&g_rowptr[warp]);
    int e = __ldg(&g_rowptr[warp + 1]);

    float2 acc = make_float2(0.f, 0.f);
    int i = s;
    for (; i + 4 <= e; i += 4) {
        int c0 = __ldg(&g_colidx[i + 0]);
        int c1 = __ldg(&g_colidx[i + 1]);
        int c2 = __ldg(&g_colidx[i + 2]);
        int c3 = __ldg(&g_colidx[i + 3]);
        float2 v0 = __ldg((const float2*)(in + (size_t)c0 * 64) + lane);
        float2 v1 = __ldg((const float2*)(in + (size_t)c1 * 64) + lane);
        float2 v2 = __ldg((const float2*)(in + (size_t)c2 * 64) + lane);
        float2 v3 = __ldg((const float2*)(in + (size_t)c3 * 64) + lane);
        acc.x += (v0.x + v1.x) + (v2.x + v3.x);
        acc.y += (v0.y + v1.y) + (v2.y + v3.y);
    }
    for (; i < e; i++) {
        int c = __ldg(&g_colidx[i]);
        float2 v = __ldg((const float2*)(in + (size_t)c * 64) + lane);
        acc.x += v.x; acc.y += v.y;
    }
    int cnt = e - s;
    float inv = 1.f / (float)(cnt > 1 ? cnt : 1);
    float2 b = __ldg((const float2*)bias + lane);
    float2 o;
    o.x = acc.x * inv + b.x;
    o.y = acc.y * inv + b.y;
    ((float2*)(out + (size_t)warp * 64))[lane] = o;
}

// ---------------- fused double GEMM: t2 = relu(A@W1 + b1) @ W2 ------------------
// BM=128 rows/block, 512 threads. Natural-layout A tile in smem (broadcast LDS),
// f32x2 packed accumulation. h1 tile is re-staged into the A-tile smem region.
__global__ void __launch_bounds__(512, 1)
fused_gemm_kernel(const float* __restrict__ A, const float* __restrict__ W1,
                  const float* __restrict__ b1, const float* __restrict__ W2,
                  float* __restrict__ T2) {
    extern __shared__ float sm[];
    float* As  = sm;               // [128][128] A tile, later h1 tile
    float* W1s = sm + 128 * 128;   // [128][128]
    float* W2s = W1s + 128 * 128;  // [128][64]
    const int tid = threadIdx.x;
    const int m0 = blockIdx.x * 128;

    // loads: W1 (16384 f), W2 (8192 f), A tile (16384 f) — all coalesced float4
    for (int i = tid * 4; i < 16384; i += 2048)
        *(float4*)&W1s[i] = *(const float4*)&W1[i];
    for (int i = tid * 4; i < 8192; i += 2048)
        *(float4*)&W2s[i] = *(const float4*)&W2[i];
    for (int i = tid * 4; i < 16384; i += 2048) {
        int r = i >> 7, c = i & 127;
        float4 v = make_float4(0.f, 0.f, 0.f, 0.f);
        if (m0 + r < N_NODES)
            v = *(const float4*)&A[(size_t)(m0 + r) * 128 + c];
        *(float4*)&As[i] = v;
    }
    __syncthreads();

    const int tx = tid & 15;   // 16 col-groups: stage1 cols tx*8..+8, stage2 tx*4..+4
    const int ty = tid >> 4;   // 32 row-groups: rows ty*4..+4

    // ---------- stage 1: h1 = relu(A @ W1 + b1), rows ty*4..+4 x cols tx*8..+8
    ull acc[4][4];
#pragma unroll
    for (int i = 0; i < 4; i++)
#pragma unroll
        for (int j = 0; j < 4; j++) acc[i][j] = 0ULL;

    for (int k0 = 0; k0 < 128; k0 += 4) {
        float4 a[4];
#pragma unroll
        for (int i = 0; i < 4; i++)
            a[i] = *(const float4*)&As[(ty * 4 + i) * 128 + k0];   // broadcast LDS
#pragma unroll
        for (int kk = 0; kk < 4; kk++) {
            float4 w0 = *(const float4*)&W1s[(k0 + kk) * 128 + tx * 8];
            float4 w1 = *(const float4*)&W1s[(k0 + kk) * 128 + tx * 8 + 4];
            ull w[4];
            w[0] = __double_as_longlong(*(double*)&w0.x);
            w[1] = __double_as_longlong(*(double*)&w0.z);
            w[2] = __double_as_longlong(*(double*)&w1.x);
            w[3] = __double_as_longlong(*(double*)&w1.z);
            ull a2[4];
            a2[0] = pack2(((const float*)&a[0])[kk]);
            a2[1] = pack2(((const float*)&a[1])[kk]);
            a2[2] = pack2(((const float*)&a[2])[kk]);
            a2[3] = pack2(((const float*)&a[3])[kk]);
#pragma unroll
            for (int i = 0; i < 4; i++)
#pragma unroll
                for (int j = 0; j < 4; j++)
                    acc[i][j] = fma2(a2[i], w[j], acc[i][j]);
        }
    }

    // bias + relu, stage into smem (overwrite As with h1 tile)
    float bias[8];
    *(float4*)&bias[0] = __ldg((const float4*)&b1[tx * 8]);
    *(float4*)&bias[4] = __ldg((const float4*)&b1[tx * 8 + 4]);
    __syncthreads();   // all stage-1 As reads complete before overwrite
#pragma unroll
    for (int i = 0; i < 4; i++) {
        float h[8];
#pragma unroll
        for (int j = 0; j < 4; j++) {
            float lo, hi;
            unpack2(acc[i][j], lo, hi);
            h[j * 2]     = fmaxf(lo + bias[j * 2], 0.f);
            h[j * 2 + 1] = fmaxf(hi + bias[j * 2 + 1], 0.f);
        }
        *(float4*)&As[(ty * 4 + i) * 128 + tx * 8]     = *(float4*)&h[0];
        *(float4*)&As[(ty * 4 + i) * 128 + tx * 8 + 4] = *(float4*)&h[4];
    }
    __syncthreads();

    // ---------- stage 2: t2 = h1 @ W2, rows ty*4..+4 x cols tx*4..+4
    ull acc2[4][2];
#pragma unroll
    for (int i = 0; i < 4; i++) { acc2[i][0] = 0ULL; acc2[i][1] = 0ULL; }

    for (int k0 = 0; k0 < 128; k0 += 4) {
        float4 a[4];
#pragma unroll
        for (int i = 0; i < 4; i++)
            a[i] = *(const float4*)&As[(ty * 4 + i) * 128 + k0];
#pragma unroll
        for (int kk = 0; kk < 4; kk++) {
            float4 wv = *(const float4*)&W2s[(k0 + kk) * 64 + tx * 4];
            ull w[2];
            w[0] = __double_as_longlong(*(double*)&wv.x);
            w[1] = __double_as_longlong(*(double*)&wv.z);
            ull a2[4];
            a2[0] = pack2(((const float*)&a[0])[kk]);
            a2[1] = pack2(((const float*)&a[1])[kk]);
            a2[2] = pack2(((const float*)&a[2])[kk]);
            a2[3] = pack2(((const float*)&a[3])[kk]);
#pragma unroll
            for (int i = 0; i < 4; i++) {
                acc2[i][0] = fma2(a2[i], w[0], acc2[i][0]);
                acc2[i][1] = fma2(a2[i], w[1], acc2[i][1]);
            }
        }
    }

#pragma unroll
    for (int i = 0; i < 4; i++) {
        int m = m0 + ty * 4 + i;
        if (m < N_NODES) {
            float o[4];
            unpack2(acc2[i][0], o[0], o[1]);
            unpack2(acc2[i][1], o[2], o[3]);
            *(float4*)&T2[(size_t)m * 64 + tx * 4] = *(float4*)&o[0];
        }
    }
}

// ---------------- launch ---------------------------------------------------------
extern "C" void kernel_launch(void* const* d_in, const int* in_sizes, int n_in,
                              void* d_out, int out_size) {
    const float* features = (const float*)d_in[0];
    const float* W1       = (const float*)d_in[1];
    const float* b1       = (const float*)d_in[2];
    const float* W2       = (const float*)d_in[3];
    const float* b2       = (const float*)d_in[4];
    const void*  src      = d_in[5];
    const void*  dst      = d_in[6];
    float*       out      = (float*)d_out;
    int E = in_sizes[5];
    if (E > MAX_E) E = MAX_E;

    float *agg_p, *t2_p;
    int   *cnt_p;
    cudaGetSymbolAddress((void**)&agg_p, g_agg);
    cudaGetSymbolAddress((void**)&t2_p,  g_t2);
    cudaGetSymbolAddress((void**)&cnt_p, g_cnt);

    const int SMEMF = (128 * 128 + 128 * 128 + 128 * 64) * 4;  // 163840 B
    cudaFuncSetAttribute(fused_gemm_kernel,
                         cudaFuncAttributeMaxDynamicSharedMemorySize, SMEMF);

    const int TB = 256;
    // CSR build
    cudaMemsetAsync(cnt_p, 0, N_NODES * sizeof(int), 0);
    detect_kernel<<<1, 256>>>((const int*)dst);
    convcount_kernel<<<(E + TB - 1) / TB, TB>>>(src, dst, E);
    scan_pass1<<<SCAN_BLOCKS, 256>>>();
    scan_pass2<<<1, 512>>>(SCAN_BLOCKS);
    scan_pass3<<<SCAN_BLOCKS, 256>>>();
    fill_kernel<<<(E + TB - 1) / TB, TB>>>(E);

    int agg_blocks = (N_NODES * 32 + TB - 1) / TB;

    // layer 0 agg, then fused relu(.@W1+b1)@W2
    agg_kernel<<<agg_blocks, TB>>>(features, agg_p);
    fused_gemm_kernel<<<(N_NODES + 127) / 128, 512, SMEMF>>>(agg_p, W1, b1, W2, t2_p);

    // layer 1 (reordered): out = S(t2) + b2
    agg64_kernel<<<agg_blocks, TB>>>(t2_p, b2, out);
}

// round 6
// speedup vs baseline: 1.7268x; 1.3069x over previous
#include <cuda_runtime.h>
#include <cuda_bf16.h>

#define N_NODES 100000
#define MAX_E   1600000
#define D       128
#define SCAN_BLOCKS ((N_NODES + 255) / 256)   // 391

typedef unsigned int u32;

// ---------------- device scratch ----------------------------------------------
__device__ int   g_src[MAX_E];
__device__ int   g_dst[MAX_E];
__device__ int   g_cnt[N_NODES];
__device__ int   g_scan[SCAN_BLOCKS * 256];
__device__ int   g_bsum[512];
__device__ int   g_rowptr[N_NODES + 1];
__device__ int   g_cursor[N_NODES];
__device__ int   g_colidx[MAX_E];
__device__ float g_agg[(size_t)N_NODES * D];   // S(X), 128-wide
__device__ float g_t2 [(size_t)N_NODES * 64];  // relu(S(X)@W1+b1) @ W2

// W fragments in mma.sync register layout: [split][kstep][nfrag][lane] uint2
__device__ uint2 g_B1f[2 * 8 * 16 * 32];   // W1: N=128 -> 16 nfrags
__device__ uint2 g_B2f[2 * 8 * 8 * 32];    // W2: N=64  -> 8 nfrags

// ---------------- helpers -------------------------------------------------------
__device__ __forceinline__ u32 pack_bf16(float lo, float hi) {
    __nv_bfloat162 t = __floats2bfloat162_rn(lo, hi);   // .x = lo half
    return *(u32*)&t;
}
__device__ __forceinline__ void mma_bf16(float* c, const u32* a, u32 b0, u32 b1) {
    asm volatile(
        "mma.sync.aligned.m16n8k16.row.col.f32.bf16.bf16.f32 "
        "{%0,%1,%2,%3}, {%4,%5,%6,%7}, {%8,%9}, {%0,%1,%2,%3};"
        : "+f"(c[0]), "+f"(c[1]), "+f"(c[2]), "+f"(c[3])
        : "r"(a[0]), "r"(a[1]), "r"(a[2]), "r"(a[3]), "r"(b0), "r"(b1));
}

// ---------------- CSR build -----------------------------------------------------
__global__ void convcount_kernel(const void* __restrict__ src,
                                 const void* __restrict__ dst, int E) {
    // inline dtype detection: odd 32-bit words of first 512 words of dst
    int v = ((const int*)dst)[(threadIdx.x & 255) * 2 + 1];
    int is64 = !__syncthreads_or(v != 0);

    int i = blockIdx.x * blockDim.x + threadIdx.x;
    if (i >= E) return;
    int s, d;
    if (is64) {
        s = (int)((const long long*)src)[i];
        d = (int)((const long long*)dst)[i];
    } else {
        s = ((const int*)src)[i];
        d = ((const int*)dst)[i];
    }
    g_src[i] = s;
    g_dst[i] = d;
    if ((unsigned)d < N_NODES) atomicAdd(&g_cnt[d], 1);
}

__global__ void scan_pass1() {
    __shared__ int s[256];
    int t = threadIdx.x;
    int i = blockIdx.x * 256 + t;
    int v = (i < N_NODES) ? g_cnt[i] : 0;
    s[t] = v;
    __syncthreads();
#pragma unroll
    for (int off = 1; off < 256; off <<= 1) {
        int x = (t >= off) ? s[t - off] : 0;
        __syncthreads();
        s[t] += x;
        __syncthreads();
    }
    g_scan[i] = s[t];
    if (t == 255) g_bsum[blockIdx.x] = s[255];
}

__global__ void scan_pass2(int nblk) {      // 512 threads, warp-shuffle scan
    int t = threadIdx.x;
    int v = (t < nblk) ? g_bsum[t] : 0;
    int x = v;
#pragma unroll
    for (int o = 1; o < 32; o <<= 1) {
        int y = __shfl_up_sync(~0u, x, o);
        if ((t & 31) >= o) x += y;
    }
    __shared__ int wsum[16];
    if ((t & 31) == 31) wsum[t >> 5] = x;
    __syncthreads();
    if (t < 16) {
        int y = wsum[t];
#pragma unroll
        for (int o = 1; o < 16; o <<= 1) {
            int z = __shfl_up_sync(0xffff, y, o);
            if (t >= o) y += z;
        }
        wsum[t] = y;
    }
    __syncthreads();
    int incl = x + ((t >= 32) ? wsum[(t >> 5) - 1] : 0);
    if (t < nblk) g_bsum[t] = incl - v;     // exclusive
}

__global__ void scan_pass3() {
    int i = blockIdx.x * blockDim.x + threadIdx.x;
    if (i >= N_NODES) return;
    int incl = g_scan[i] + g_bsum[i >> 8];
    g_rowptr[i + 1] = incl;
    g_cursor[i] = incl - g_cnt[i];
    if (i == 0) g_rowptr[0] = 0;
}

__global__ void fill_kernel(int E) {
    int i = blockIdx.x * blockDim.x + threadIdx.x;
    if (i >= E) return;
    unsigned d = (unsigned)g_dst[i];
    unsigned s = (unsigned)g_src[i];
    if (d >= N_NODES || s >= N_NODES) return;
    int pos = atomicAdd(&g_cursor[d], 1);
    g_colidx[pos] = (int)s;
}

// ---------------- aggregations ---------------------------------------------------
__global__ void agg_kernel(const float* __restrict__ in, float* __restrict__ out) {
    int warp = (blockIdx.x * blockDim.x + threadIdx.x) >> 5;
    int lane = threadIdx.x & 31;
    if (warp >= N_NODES) return;
    int s = __ldg(&g_rowptr[warp]);
    int e = __ldg(&g_rowptr[warp + 1]);
    float4 acc = make_float4(0.f, 0.f, 0.f, 0.f);
    int i = s;
    for (; i + 4 <= e; i += 4) {
        int c0 = __ldg(&g_colidx[i + 0]);
        int c1 = __ldg(&g_colidx[i + 1]);
        int c2 = __ldg(&g_colidx[i + 2]);
        int c3 = __ldg(&g_colidx[i + 3]);
        float4 v0 = __ldg((const float4*)(in + (size_t)c0 * D) + lane);
        float4 v1 = __ldg((const float4*)(in + (size_t)c1 * D) + lane);
        float4 v2 = __ldg((const float4*)(in + (size_t)c2 * D) + lane);
        float4 v3 = __ldg((const float4*)(in + (size_t)c3 * D) + lane);
        acc.x += (v0.x + v1.x) + (v2.x + v3.x);
        acc.y += (v0.y + v1.y) + (v2.y + v3.y);
        acc.z += (v0.z + v1.z) + (v2.z + v3.z);
        acc.w += (v0.w + v1.w) + (v2.w + v3.w);
    }
    for (; i < e; i++) {
        int c = __ldg(&g_colidx[i]);
        float4 v = __ldg((const float4*)(in + (size_t)c * D) + lane);
        acc.x += v.x; acc.y += v.y; acc.z += v.z; acc.w += v.w;
    }
    int cnt = e - s;
    float inv = 1.f / (float)(cnt > 1 ? cnt : 1);
    acc.x *= inv; acc.y *= inv; acc.z *= inv; acc.w *= inv;
    ((float4*)(out + (size_t)warp * D))[lane] = acc;
}

__global__ void agg64_kernel(const float* __restrict__ in,
                             const float* __restrict__ bias,
                             float* __restrict__ out) {
    int warp = (blockIdx.x * blockDim.x + threadIdx.x) >> 5;
    int lane = threadIdx.x & 31;
    if (warp >= N_NODES) return;
    int s = __ldg(&g_rowptr[warp]);
    int e = __ldg(&g_rowptr[warp + 1]);
    float2 acc = make_float2(0.f, 0.f);
    int i = s;
    for (; i + 4 <= e; i += 4) {
        int c0 = __ldg(&g_colidx[i + 0]);
        int c1 = __ldg(&g_colidx[i + 1]);
        int c2 = __ldg(&g_colidx[i + 2]);
        int c3 = __ldg(&g_colidx[i + 3]);
        float2 v0 = __ldg((const float2*)(in + (size_t)c0 * 64) + lane);
        float2 v1 = __ldg((const float2*)(in + (size_t)c1 * 64) + lane);
        float2 v2 = __ldg((const float2*)(in + (size_t)c2 * 64) + lane);
        float2 v3 = __ldg((const float2*)(in + (size_t)c3 * 64) + lane);
        acc.x += (v0.x + v1.x) + (v2.x + v3.x);
        acc.y += (v0.y + v1.y) + (v2.y + v3.y);
    }
    for (; i < e; i++) {
        int c = __ldg(&g_colidx[i]);
        float2 v = __ldg((const float2*)(in + (size_t)c * 64) + lane);
        acc.x += v.x; acc.y += v.y;
    }
    int cnt = e - s;
    float inv = 1.f / (float)(cnt > 1 ? cnt : 1);
    float2 b = __ldg((const float2*)bias + lane);
    float2 o;
    o.x = acc.x * inv + b.x;
    o.y = acc.y * inv + b.y;
    ((float2*)(out + (size_t)warp * 64))[lane] = o;
}

// ---------------- W fp32 -> hi/lo bf16 mma fragments -----------------------------
// B frag (m16n8k16, col): lane l -> n = nf*8 + l/4; b0 halves = W[k][n],W[k+1][n]
// with k = ks*16 + (l%4)*2; b1 halves at k+8.
__global__ void wconv_kernel(const float* __restrict__ W1, const float* __restrict__ W2) {
    int i = blockIdx.x * blockDim.x + threadIdx.x;
    if (i < 4096) {                          // W1: 8 ks x 16 nf x 32 lanes
        int lane = i & 31, nf = (i >> 5) & 15, ks = i >> 9;
        int k = ks * 16 + (lane & 3) * 2;
        int n = nf * 8 + (lane >> 2);
        float w00 = W1[k * 128 + n],       w01 = W1[(k + 1) * 128 + n];
        float w10 = W1[(k + 8) * 128 + n], w11 = W1[(k + 9) * 128 + n];
        float h00 = __bfloat162float(__float2bfloat16(w00));
        float h01 = __bfloat162float(__float2bfloat16(w01));
        float h10 = __bfloat162float(__float2bfloat16(w10));
        float h11 = __bfloat162float(__float2bfloat16(w11));
        uint2 hi, lo;
        hi.x = pack_bf16(h00, h01);          hi.y = pack_bf16(h10, h11);
        lo.x = pack_bf16(w00 - h00, w01 - h01);
        lo.y = pack_bf16(w10 - h10, w11 - h11);
        g_B1f[(ks * 16 + nf) * 32 + lane]          = hi;
        g_B1f[((8 + ks) * 16 + nf) * 32 + lane]    = lo;   // split 1 block
    } else if (i < 6144) {                   // W2: 8 ks x 8 nf x 32 lanes
        int j = i - 4096;
        int lane = j & 31, nf = (j >> 5) & 7, ks = j >> 8;
        int k = ks * 16 + (lane & 3) * 2;
        int n = nf * 8 + (lane >> 2);
        float w00 = W2[k * 64 + n],       w01 = W2[(k + 1) * 64 + n];
        float w10 = W2[(k + 8) * 64 + n], w11 = W2[(k + 9) * 64 + n];
        float h00 = __bfloat162float(__float2bfloat16(w00));
        float h01 = __bfloat162float(__float2bfloat16(w01));
        float h10 = __bfloat162float(__float2bfloat16(w10));
        float h11 = __bfloat162float(__float2bfloat16(w11));
        uint2 hi, lo;
        hi.x = pack_bf16(h00, h01);          hi.y = pack_bf16(h10, h11);
        lo.x = pack_bf16(w00 - h00, w01 - h01);
        lo.y = pack_bf16(w10 - h10, w11 - h11);
        g_B2f[(ks * 8 + nf) * 32 + lane]        = hi;
        g_B2f[((8 + ks) * 8 + nf) * 32 + lane]  = lo;
    }
}

// ---------------- fused double GEMM via HMMA (3x bf16 split) ---------------------
// t2 = relu(A @ W1 + b1) @ W2. CTA = 128 rows, 256 thr (8 warps, 4Mx2N grid).
// A tile stored hi/lo bf16 in smem, padded row stride 68 u32 (136 halves).
#define ASTRIDE 68
#define SM_B1   0                            // 512 B bias
#define SM_AHI  512                          // 128*68*4 = 34816
#define SM_ALO  (SM_AHI + 34816)
#define SM_BF1  (SM_ALO + 34816)             // 65536
#define SM_BF2  (SM_BF1 + 65536)             // 32768
#define SM_TOT  (SM_BF2 + 32768)             // 168448

__global__ void __launch_bounds__(256, 1)
gemm_hmma_kernel(const float* __restrict__ A, const float* __restrict__ b1,
                 float* __restrict__ T2) {
    extern __shared__ char smem[];
    float* b1s    = (float*)(smem + SM_B1);
    u32*   Ahi    = (u32*)(smem + SM_AHI);
    u32*   Alo    = (u32*)(smem + SM_ALO);
    uint2* Bs1    = (uint2*)(smem + SM_BF1);
    uint2* Bs2    = (uint2*)(smem + SM_BF2);

    const int tid  = threadIdx.x;
    const int lane = tid & 31;
    const int wid  = tid >> 5;
    const int wm   = wid & 3;      // 4 M-groups of 32 rows
    const int wn   = wid >> 2;     // 2 N-groups
    const int m0   = blockIdx.x * 128;

    // stage B fragments + bias
    {
        const uint4* s1 = (const uint4*)g_B1f;
        const uint4* s2 = (const uint4*)g_B2f;
        uint4* d1 = (uint4*)Bs1;
        uint4* d2 = (uint4*)Bs2;
        for (int i = tid; i < 4096; i += 256) d1[i] = s1[i];
        for (int i = tid; i < 2048; i += 256) d2[i] = s2[i];
        if (tid < 32) ((float4*)b1s)[tid] = ((const float4*)b1)[tid];
    }

    // load A tile (128x128 fp32) -> hi/lo bf16, padded layout
    for (int i = tid * 4; i < 16384; i += 1024) {
        int r = i >> 7, c = i & 127;
        float4 v = make_float4(0.f, 0.f, 0.f, 0.f);
        if (m0 + r < N_NODES)
            v = *(const float4*)&A[(size_t)(m0 + r) * 128 + c];
        float hx = __bfloat162float(__float2bfloat16(v.x));
        float hy = __bfloat162float(__float2bfloat16(v.y));
        float hz = __bfloat162float(__float2bfloat16(v.z));
        float hw = __bfloat162float(__float2bfloat16(v.w));
        uint2 hp, lp;
        hp.x = pack_bf16(hx, hy);            hp.y = pack_bf16(hz, hw);
        lp.x = pack_bf16(v.x - hx, v.y - hy); lp.y = pack_bf16(v.z - hz, v.w - hw);
        *(uint2*)&Ahi[r * ASTRIDE + (c >> 1)] = hp;
        *(uint2*)&Alo[r * ASTRIDE + (c >> 1)] = lp;
    }
    __syncthreads();

    // ---------------- stage 1: D1 = A @ W1  (M128 x N128) -----------------------
    float acc[2][8][4];
#pragma unroll
    for (int mf = 0; mf < 2; mf++)
#pragma unroll
        for (int nf = 0; nf < 8; nf++)
#pragma unroll
            for (int q = 0; q < 4; q++) acc[mf][nf][q] = 0.f;

    const int arow = (lane >> 2);
    const int acol = (lane & 3);
#pragma unroll
    for (int ks = 0; ks < 8; ks++) {
        int cb = ks * 8 + acol;
        u32 ah[2][4], al[2][4];
#pragma unroll
        for (int mf = 0; mf < 2; mf++) {
            int r = wm * 32 + mf * 16 + arow;
            ah[mf][0] = Ahi[r * ASTRIDE + cb];
            ah[mf][1] = Ahi[(r + 8) * ASTRIDE + cb];
            ah[mf][2] = Ahi[r * ASTRIDE + cb + 4];
            ah[mf][3] = Ahi[(r + 8) * ASTRIDE + cb + 4];
            al[mf][0] = Alo[r * ASTRIDE + cb];
            al[mf][1] = Alo[(r + 8) * ASTRIDE + cb];
            al[mf][2] = Alo[r * ASTRIDE + cb + 4];
            al[mf][3] = Alo[(r + 8) * ASTRIDE + cb + 4];
        }
#pragma unroll
        for (int nf = 0; nf < 8; nf++) {
            int nfg = wn * 8 + nf;
            uint2 bh = Bs1[(ks * 16 + nfg) * 32 + lane];
            uint2 bl = Bs1[((8 + ks) * 16 + nfg) * 32 + lane];
#pragma unroll
            for (int mf = 0; mf < 2; mf++) {
                mma_bf16(acc[mf][nf], ah[mf], bh.x, bh.y);
                mma_bf16(acc[mf][nf], ah[mf], bl.x, bl.y);
                mma_bf16(acc[mf][nf], al[mf], bh.x, bh.y);
            }
        }
    }
    __syncthreads();   // all stage-1 A reads complete before overwrite

    // epilogue 1: h1 = relu(D1 + b1) -> hi/lo bf16 back into A smem
#pragma unroll
    for (int mf = 0; mf < 2; mf++) {
#pragma unroll
        for (int nf = 0; nf < 8; nf++) {
            int r   = wm * 32 + mf * 16 + arow;
            int col = wn * 64 + nf * 8 + acol * 2;
            float bb0 = b1s[col], bb1 = b1s[col + 1];
            float x0 = fmaxf(acc[mf][nf][0] + bb0, 0.f);
            float x1 = fmaxf(acc[mf][nf][1] + bb1, 0.f);
            float x2 = fmaxf(acc[mf][nf][2] + bb0, 0.f);
            float x3 = fmaxf(acc[mf][nf][3] + bb1, 0.f);
            float h0 = __bfloat162float(__float2bfloat16(x0));
            float h1 = __bfloat162float(__float2bfloat16(x1));
            float h2 = __bfloat162float(__float2bfloat16(x2));
            float h3 = __bfloat162float(__float2bfloat16(x3));
            Ahi[r * ASTRIDE + (col >> 1)]       = pack_bf16(h0, h1);
            Alo[r * ASTRIDE + (col >> 1)]       = pack_bf16(x0 - h0, x1 - h1);
            Ahi[(r + 8) * ASTRIDE + (col >> 1)] = pack_bf16(h2, h3);
            Alo[(r + 8) * ASTRIDE + (col >> 1)] = pack_bf16(x2 - h2, x3 - h3);
        }
    }
    __syncthreads();

    // ---------------- stage 2: t2 = h1 @ W2  (M128 x N64) -----------------------
    float acc2[2][4][4];
#pragma unroll
    for (int mf = 0; mf < 2; mf++)
#pragma unroll
        for (int nf = 0; nf < 4; nf++)
#pragma unroll
            for (int q = 0; q < 4; q++) acc2[mf][nf][q] = 0.f;

#pragma unroll
    for (int ks = 0; ks < 8; ks++) {
        int cb = ks * 8 + acol;
        u32 ah[2][4], al[2][4];
#pragma unroll
        for (int mf = 0; mf < 2; mf++) {
            int r = wm * 32 + mf * 16 + arow;
            ah[mf][0] = Ahi[r * ASTRIDE + cb];
            ah[mf][1] = Ahi[(r + 8) * ASTRIDE + cb];
            ah[mf][2] = Ahi[r * ASTRIDE + cb + 4];
            ah[mf][3] = Ahi[(r + 8) * ASTRIDE + cb + 4];
            al[mf][0] = Alo[r * ASTRIDE + cb];
            al[mf][1] = Alo[(r + 8) * ASTRIDE + cb];
            al[mf][2] = Alo[r * ASTRIDE + cb + 4];
            al[mf][3] = Alo[(r + 8) * ASTRIDE + cb + 4];
        }
#pragma unroll
        for (int nf = 0; nf < 4; nf++) {
            int nfg = wn * 4 + nf;
            uint2 bh = Bs2[(ks * 8 + nfg) * 32 + lane];
            uint2 bl = Bs2[((8 + ks) * 8 + nfg) * 32 + lane];
#pragma unroll
            for (int mf = 0; mf < 2; mf++) {
                mma_bf16(acc2[mf][nf], ah[mf], bh.x, bh.y);
                mma_bf16(acc2[mf][nf], ah[mf], bl.x, bl.y);
                mma_bf16(acc2[mf][nf], al[mf], bh.x, bh.y);
            }
        }
    }

    // epilogue 2: write t2
#pragma unroll
    for (int mf = 0; mf < 2; mf++) {
#pragma unroll
        for (int nf = 0; nf < 4; nf++) {
            int r   = m0 + wm * 32 + mf * 16 + arow;
            int col = wn * 32 + nf * 8 + acol * 2;
            if (r < N_NODES) {
                float2 v0 = make_float2(acc2[mf][nf][0], acc2[mf][nf][1]);
                *(float2*)&T2[(size_t)r * 64 + col] = v0;
            }
            if (r + 8 < N_NODES) {
                float2 v1 = make_float2(acc2[mf][nf][2], acc2[mf][nf][3]);
                *(float2*)&T2[(size_t)(r + 8) * 64 + col] = v1;
            }
        }
    }
}

// ---------------- launch ---------------------------------------------------------
extern "C" void kernel_launch(void* const* d_in, const int* in_sizes, int n_in,
                              void* d_out, int out_size) {
    const float* features = (const float*)d_in[0];
    const float* W1       = (const float*)d_in[1];
    const float* b1       = (const float*)d_in[2];
    const float* W2       = (const float*)d_in[3];
    const float* b2       = (const float*)d_in[4];
    const void*  src      = d_in[5];
    const void*  dst      = d_in[6];
    float*       out      = (float*)d_out;
    int E = in_sizes[5];
    if (E > MAX_E) E = MAX_E;

    float *agg_p, *t2_p;
    int   *cnt_p;
    cudaGetSymbolAddress((void**)&agg_p, g_agg);
    cudaGetSymbolAddress((void**)&t2_p,  g_t2);
    cudaGetSymbolAddress((void**)&cnt_p, g_cnt);

    cudaFuncSetAttribute(gemm_hmma_kernel,
                         cudaFuncAttributeMaxDynamicSharedMemorySize, SM_TOT);

    const int TB = 256;
    cudaMemsetAsync(cnt_p, 0, N_NODES * sizeof(int), 0);
    wconv_kernel<<<24, 256>>>(W1, W2);
    convcount_kernel<<<(E + TB - 1) / TB, TB>>>(src, dst, E);
    scan_pass1<<<SCAN_BLOCKS, 256>>>();
    scan_pass2<<<1, 512>>>(SCAN_BLOCKS);
    scan_pass3<<<SCAN_BLOCKS, 256>>>();
    fill_kernel<<<(E + TB - 1) / TB, TB>>>(E);

    int agg_blocks = (N_NODES * 32 + TB - 1) / TB;
    agg_kernel<<<agg_blocks, TB>>>(features, agg_p);
    gemm_hmma_kernel<<<(N_NODES + 127) / 128, 256, SM_TOT>>>(agg_p, b1, t2_p);
    agg64_kernel<<<agg_blocks, TB>>>(t2_p, b2, out);
}